// round 8
// baseline (speedup 1.0000x reference)
#include <cuda_runtime.h>
#include <cuda_bf16.h>

#define B    8
#define C    256
#define HW4  16384                              // float4 per (b,c) plane
#define F4_PER_BLOCK  1024                      // 4 float4/thread * 256 threads
#define BLOCKS_PER_PLANE (HW4 / F4_PER_BLOCK)   // 16
#define NBLOCKS ((B * C) * BLOCKS_PER_PLANE)    // 32768
#define GATE_BLOCKS 256u

// Scratch (no allocation allowed -> __device__ globals). All counters are
// monotone (epoch-encoded), never reset -> deterministic across graph replays.
__device__ float g_h[B * C];
__device__ float g_logits[B * C];
__device__ float g_scale[B * C];
__device__ unsigned int g_entry;                // per-block entry -> epoch
__device__ unsigned int g_bar1, g_bar2;         // gate-internal grid barriers
__device__ unsigned int g_release;              // gate-done release counter

// Epoch grid barrier among the GATE_BLOCKS gate blocks (wave-1 co-resident:
// 32 regs, 256 thr -> 8 blocks/SM -> 1184 resident >= 256).
__device__ __forceinline__ void gate_barrier(unsigned int* bar) {
    __threadfence();
    __syncthreads();
    if (threadIdx.x == 0) {
        unsigned int v = atomicAdd(bar, 1u);
        unsigned int target = (v / GATE_BLOCKS + 1u) * GATE_BLOCKS;
        volatile unsigned int* vb = bar;
        while (*vb < target) { }
    }
    __syncthreads();
    __threadfence();
}

// ---------------------------------------------------------------------------
// Single fused kernel, reg-capped to 32 (launch_bounds minBlocks=8) so the
// cold gate path cannot tax the hot stream path's occupancy.
//  * all blocks: prefetch 4 float4 of x (reads start immediately, chip-wide)
//  * blocks 0..255: gate (2 matvec layers + softmax) -> g_scale -> release
//  * all blocks: spin until release(epoch), then scale + store.
// ---------------------------------------------------------------------------
__global__ void __launch_bounds__(256, 8) fused_kernel(const float4* __restrict__ x,
                                                       float4* __restrict__ y,
                                                       const float* __restrict__ semantic,
                                                       const float* __restrict__ W1,
                                                       const float* __restrict__ b1,
                                                       const float* __restrict__ W2,
                                                       const float* __restrict__ b2) {
    const int blk = blockIdx.x;
    const int tid = threadIdx.x;

    // ---- stream prefetch (issue before any waiting) -----------------------
    const size_t i0 = (size_t)blk * F4_PER_BLOCK + tid;
    float4 v0 = __ldcs(x + i0);
    float4 v1 = __ldcs(x + i0 + 256);
    float4 v2 = __ldcs(x + i0 + 512);
    float4 v3 = __ldcs(x + i0 + 768);

    // ---- per-block epoch (monotone across replays) ------------------------
    __shared__ unsigned int s_epoch;
    if (tid == 0) s_epoch = atomicAdd(&g_entry, 1u) / (unsigned)NBLOCKS;

    // ---- gate (blocks 0..255 only; cold path, spills are fine) ------------
    if (blk < (int)GATE_BLOCKS) {
        const int lane = tid & 31;
        const int wg   = blk * 8 + (tid >> 5);   // 0..2047
        const int b    = wg >> 8;
        const int c    = wg & 255;

        // Layer 1: g_h = leaky_relu(semantic @ W1^T + b1)
        {
            const float4* __restrict__ w4 = (const float4*)(W1 + c * C);
            const float4* __restrict__ i4 = (const float4*)(semantic + b * C);
            float4 wa = __ldg(w4 + lane), wb = __ldg(w4 + lane + 32);
            float4 ia = __ldg(i4 + lane), ib = __ldg(i4 + lane + 32);
            float p = wa.x*ia.x + wa.y*ia.y + wa.z*ia.z + wa.w*ia.w
                    + wb.x*ib.x + wb.y*ib.y + wb.z*ib.z + wb.w*ib.w;
            #pragma unroll
            for (int s = 16; s > 0; s >>= 1) p += __shfl_xor_sync(0xffffffffu, p, s);
            if (lane == 0) {
                float r = p + __ldg(b1 + c);
                g_h[b * C + c] = r > 0.0f ? r : 0.1f * r;
            }
        }
        gate_barrier(&g_bar1);

        // Layer 2: g_logits = g_h @ W2^T + b2
        {
            const float4* __restrict__ w4 = (const float4*)(W2 + c * C);
            const float4* __restrict__ i4 = (const float4*)(g_h + b * C);
            float4 wa = __ldg(w4 + lane), wb = __ldg(w4 + lane + 32);
            float4 ia = i4[lane], ib = i4[lane + 32];
            float p = wa.x*ia.x + wa.y*ia.y + wa.z*ia.z + wa.w*ia.w
                    + wb.x*ib.x + wb.y*ib.y + wb.z*ib.z + wb.w*ib.w;
            #pragma unroll
            for (int s = 16; s > 0; s >>= 1) p += __shfl_xor_sync(0xffffffffu, p, s);
            if (lane == 0) g_logits[b * C + c] = p + __ldg(b2 + c);
        }
        gate_barrier(&g_bar2);

        // Softmax: blocks 0..7 handle batch rows 0..7 -> g_scale
        if (blk < B) {
            __shared__ float red[C];
            const float logit = g_logits[blk * C + tid];
            red[tid] = logit;
            __syncthreads();
            #pragma unroll
            for (int s = 128; s > 0; s >>= 1) {
                if (tid < s) red[tid] = fmaxf(red[tid], red[tid + s]);
                __syncthreads();
            }
            const float m = red[0];
            __syncthreads();
            const float e = __expf(logit - m);
            red[tid] = e;
            __syncthreads();
            #pragma unroll
            for (int s = 128; s > 0; s >>= 1) {
                if (tid < s) red[tid] += red[tid + s];
                __syncthreads();
            }
            g_scale[blk * C + tid] = 1.0f + e / red[0];
        }

        // Release: one arrival per gate block, after g_scale globally visible.
        __syncthreads();
        if (tid == 0) {
            __threadfence();
            atomicAdd(&g_release, 1u);
        }
    }

    // ---- wait for this launch's gate to complete --------------------------
    __syncthreads();                      // s_epoch visible to all threads
    if (tid == 0) {
        const unsigned int target = (s_epoch + 1u) * GATE_BLOCKS;
        volatile unsigned int* vr = &g_release;
        while (*vr < target) __nanosleep(32);
    }
    __syncthreads();
    __threadfence();                      // acquire: g_scale writes visible

    // ---- scale + store ----------------------------------------------------
    const float s = __ldg(&g_scale[blk >> 4]);   // / BLOCKS_PER_PLANE

    v0.x *= s; v0.y *= s; v0.z *= s; v0.w *= s;
    v1.x *= s; v1.y *= s; v1.z *= s; v1.w *= s;
    v2.x *= s; v2.y *= s; v2.z *= s; v2.w *= s;
    v3.x *= s; v3.y *= s; v3.z *= s; v3.w *= s;

    __stcs(y + i0,       v0);
    __stcs(y + i0 + 256, v1);
    __stcs(y + i0 + 512, v2);
    __stcs(y + i0 + 768, v3);
}

extern "C" void kernel_launch(void* const* d_in, const int* in_sizes, int n_in,
                              void* d_out, int out_size) {
    const float* x        = (const float*)d_in[0];
    const float* semantic = (const float*)d_in[1];
    const float* W1       = (const float*)d_in[2];
    const float* b1       = (const float*)d_in[3];
    const float* W2       = (const float*)d_in[4];
    const float* b2       = (const float*)d_in[5];
    float* out = (float*)d_out;

    fused_kernel<<<NBLOCKS, 256>>>((const float4*)x, (float4*)out,
                                   semantic, W1, b1, W2, b2);
}

// round 9
// speedup vs baseline: 1.0863x; 1.0863x over previous
#include <cuda_runtime.h>
#include <cuda_bf16.h>

#define B    8
#define C    256
#define HW4  16384                              // float4 per (b,c) plane
#define F4_PER_BLOCK  1024                      // 4 float4/thread * 256 threads
#define BLOCKS_PER_PLANE (HW4 / F4_PER_BLOCK)   // 16
#define NBLOCKS ((B * C) * BLOCKS_PER_PLANE)    // 32768
#define GATE_BLOCKS 256u

// Scratch (no allocation allowed -> __device__ globals). All counters are
// monotone (epoch-encoded), never reset -> deterministic across graph replays.
__device__ float g_h[B * C];
__device__ float g_logits[B * C];
__device__ float g_scale[B * C];
__device__ unsigned int g_entry;                // per-block entry -> epoch
__device__ unsigned int g_bar1, g_bar2;         // gate-internal grid barriers
__device__ unsigned int g_release;              // gate-done release counter

// Epoch grid barrier among the GATE_BLOCKS gate blocks (wave-1 co-resident:
// <=32 regs, 256 thr -> 8 blocks/SM -> 1184 resident >= 256 -> no deadlock).
__device__ __forceinline__ void gate_barrier(unsigned int* bar) {
    __threadfence();
    __syncthreads();
    if (threadIdx.x == 0) {
        unsigned int v = atomicAdd(bar, 1u);
        unsigned int target = (v / GATE_BLOCKS + 1u) * GATE_BLOCKS;
        volatile unsigned int* vb = bar;
        while (*vb < target) { }
    }
    __syncthreads();
    __threadfence();
}

// ---------------------------------------------------------------------------
// Single fused kernel, reg-capped to 32. KEY vs R8: nothing is live across
// the release wait in the hot path -> no hot-path spills. Order is:
//   epoch -> [gate if blk<256] -> wait(release) -> load -> scale -> store.
// ---------------------------------------------------------------------------
__global__ void __launch_bounds__(256, 8) fused_kernel(const float4* __restrict__ x,
                                                       float4* __restrict__ y,
                                                       const float* __restrict__ semantic,
                                                       const float* __restrict__ W1,
                                                       const float* __restrict__ b1,
                                                       const float* __restrict__ W2,
                                                       const float* __restrict__ b2) {
    const int blk = blockIdx.x;
    const int tid = threadIdx.x;

    // ---- per-block epoch (monotone across replays) ------------------------
    __shared__ unsigned int s_epoch;
    if (tid == 0) s_epoch = atomicAdd(&g_entry, 1u) / (unsigned)NBLOCKS;

    // ---- gate (blocks 0..255 only; cold path, minor spills are fine) ------
    if (blk < (int)GATE_BLOCKS) {
        const int lane = tid & 31;
        const int wg   = blk * 8 + (tid >> 5);   // 0..2047
        const int b    = wg >> 8;
        const int c    = wg & 255;

        // Layer 1: g_h = leaky_relu(semantic @ W1^T + b1)
        {
            const float4* __restrict__ w4 = (const float4*)(W1 + c * C);
            const float4* __restrict__ i4 = (const float4*)(semantic + b * C);
            float4 wa = __ldg(w4 + lane), wb = __ldg(w4 + lane + 32);
            float4 ia = __ldg(i4 + lane), ib = __ldg(i4 + lane + 32);
            float p = wa.x*ia.x + wa.y*ia.y + wa.z*ia.z + wa.w*ia.w
                    + wb.x*ib.x + wb.y*ib.y + wb.z*ib.z + wb.w*ib.w;
            #pragma unroll
            for (int s = 16; s > 0; s >>= 1) p += __shfl_xor_sync(0xffffffffu, p, s);
            if (lane == 0) {
                float r = p + __ldg(b1 + c);
                g_h[b * C + c] = r > 0.0f ? r : 0.1f * r;
            }
        }
        gate_barrier(&g_bar1);

        // Layer 2: g_logits = g_h @ W2^T + b2
        {
            const float4* __restrict__ w4 = (const float4*)(W2 + c * C);
            const float4* __restrict__ i4 = (const float4*)(g_h + b * C);
            float4 wa = __ldg(w4 + lane), wb = __ldg(w4 + lane + 32);
            float4 ia = i4[lane], ib = i4[lane + 32];
            float p = wa.x*ia.x + wa.y*ia.y + wa.z*ia.z + wa.w*ia.w
                    + wb.x*ib.x + wb.y*ib.y + wb.z*ib.z + wb.w*ib.w;
            #pragma unroll
            for (int s = 16; s > 0; s >>= 1) p += __shfl_xor_sync(0xffffffffu, p, s);
            if (lane == 0) g_logits[b * C + c] = p + __ldg(b2 + c);
        }
        gate_barrier(&g_bar2);

        // Softmax: blocks 0..7 handle batch rows 0..7 -> g_scale
        if (blk < B) {
            __shared__ float red[C];
            const float logit = g_logits[blk * C + tid];
            red[tid] = logit;
            __syncthreads();
            #pragma unroll
            for (int s = 128; s > 0; s >>= 1) {
                if (tid < s) red[tid] = fmaxf(red[tid], red[tid + s]);
                __syncthreads();
            }
            const float m = red[0];
            __syncthreads();
            const float e = __expf(logit - m);
            red[tid] = e;
            __syncthreads();
            #pragma unroll
            for (int s = 128; s > 0; s >>= 1) {
                if (tid < s) red[tid] += red[tid + s];
                __syncthreads();
            }
            g_scale[blk * C + tid] = 1.0f + e / red[0];
        }

        // Release: one arrival per gate block. Counting to 256 implies blocks
        // 0..7 (softmax writers) have arrived, i.e., g_scale is complete.
        __syncthreads();
        if (tid == 0) {
            __threadfence();
            atomicAdd(&g_release, 1u);
        }
    }

    // ---- wait for this launch's gate to complete (nothing live here) ------
    __syncthreads();                      // s_epoch visible to all threads
    if (tid == 0) {
        const unsigned int target = (s_epoch + 1u) * GATE_BLOCKS;
        volatile unsigned int* vr = &g_release;
        while (*vr < target) __nanosleep(32);
    }
    __syncthreads();
    __threadfence();                      // acquire: g_scale writes visible

    // ---- stream: load -> scale -> store (lean, ~26 regs) ------------------
    const float s = __ldg(&g_scale[blk >> 4]);   // / BLOCKS_PER_PLANE
    const size_t i0 = (size_t)blk * F4_PER_BLOCK + tid;

    float4 v0 = __ldcs(x + i0);
    float4 v1 = __ldcs(x + i0 + 256);
    float4 v2 = __ldcs(x + i0 + 512);
    float4 v3 = __ldcs(x + i0 + 768);

    v0.x *= s; v0.y *= s; v0.z *= s; v0.w *= s;
    v1.x *= s; v1.y *= s; v1.z *= s; v1.w *= s;
    v2.x *= s; v2.y *= s; v2.z *= s; v2.w *= s;
    v3.x *= s; v3.y *= s; v3.z *= s; v3.w *= s;

    __stcs(y + i0,       v0);
    __stcs(y + i0 + 256, v1);
    __stcs(y + i0 + 512, v2);
    __stcs(y + i0 + 768, v3);
}

extern "C" void kernel_launch(void* const* d_in, const int* in_sizes, int n_in,
                              void* d_out, int out_size) {
    const float* x        = (const float*)d_in[0];
    const float* semantic = (const float*)d_in[1];
    const float* W1       = (const float*)d_in[2];
    const float* b1       = (const float*)d_in[3];
    const float* W2       = (const float*)d_in[4];
    const float* b2       = (const float*)d_in[5];
    float* out = (float*)d_out;

    fused_kernel<<<NBLOCKS, 256>>>((const float4*)x, (float4*)out,
                                   semantic, W1, b1, W2, b2);
}

// round 10
// speedup vs baseline: 1.1003x; 1.0129x over previous
#include <cuda_runtime.h>
#include <cuda_bf16.h>

#define B    8
#define C    256
#define HW4  16384                              // float4 per (b,c) plane
#define F4_PER_BLOCK  1024                      // 4 float4/thread * 256 threads
#define BLOCKS_PER_PLANE (HW4 / F4_PER_BLOCK)   // 16
#define GATE_BLOCKS 256

// Scratch (no allocation allowed -> __device__ globals)
__device__ float g_h[B * C];
__device__ float g_logits[B * C];
__device__ float g_scale[B * C];
__device__ unsigned int g_bar1, g_bar2;         // epoch-counting grid barriers

// Epoch-based grid barrier: never reset, monotone across graph replays.
// 256 blocks x 256 thr, <=32 regs -> all co-resident (148 SMs) -> no deadlock.
__device__ __forceinline__ void grid_barrier(unsigned int* bar, unsigned int nb) {
    __threadfence();
    __syncthreads();
    if (threadIdx.x == 0) {
        unsigned int v = atomicAdd(bar, 1u);
        unsigned int target = (v / nb + 1u) * nb;
        volatile unsigned int* vb = bar;
        while (*vb < target) { }
    }
    __syncthreads();
    __threadfence();
}

// ---------------------------------------------------------------------------
// Node 1 — gate: layer1 -> barrier -> layer2 -> barrier -> softmax.
// 256 blocks x 256 threads; warp-per-output coalesced float4 matvecs.
// All sync overhead stays in this tiny kernel, OUTSIDE the stream kernel.
// ---------------------------------------------------------------------------
__global__ void __launch_bounds__(256) gate_kernel(const float* __restrict__ semantic,
                                                   const float* __restrict__ W1,
                                                   const float* __restrict__ b1,
                                                   const float* __restrict__ W2,
                                                   const float* __restrict__ b2) {
    const int tid  = threadIdx.x;
    const int lane = tid & 31;
    const int wg   = blockIdx.x * 8 + (tid >> 5);   // 0..2047
    const int b    = wg >> 8;
    const int c    = wg & 255;

    // -------- Layer 1: g_h = leaky_relu(semantic @ W1^T + b1) --------------
    {
        const float4* __restrict__ w4 = (const float4*)(W1 + c * C);
        const float4* __restrict__ i4 = (const float4*)(semantic + b * C);
        float4 wa = __ldg(w4 + lane), wb = __ldg(w4 + lane + 32);
        float4 ia = __ldg(i4 + lane), ib = __ldg(i4 + lane + 32);
        float p = wa.x*ia.x + wa.y*ia.y + wa.z*ia.z + wa.w*ia.w
                + wb.x*ib.x + wb.y*ib.y + wb.z*ib.z + wb.w*ib.w;
        #pragma unroll
        for (int s = 16; s > 0; s >>= 1) p += __shfl_xor_sync(0xffffffffu, p, s);
        if (lane == 0) {
            float r = p + __ldg(b1 + c);
            g_h[b * C + c] = r > 0.0f ? r : 0.1f * r;
        }
    }
    grid_barrier(&g_bar1, GATE_BLOCKS);

    // -------- Layer 2: g_logits = g_h @ W2^T + b2 --------------------------
    {
        const float4* __restrict__ w4 = (const float4*)(W2 + c * C);
        const float4* __restrict__ i4 = (const float4*)(g_h + b * C);
        float4 wa = __ldg(w4 + lane), wb = __ldg(w4 + lane + 32);
        float4 ia = i4[lane], ib = i4[lane + 32];
        float p = wa.x*ia.x + wa.y*ia.y + wa.z*ia.z + wa.w*ia.w
                + wb.x*ib.x + wb.y*ib.y + wb.z*ib.z + wb.w*ib.w;
        #pragma unroll
        for (int s = 16; s > 0; s >>= 1) p += __shfl_xor_sync(0xffffffffu, p, s);
        if (lane == 0) g_logits[b * C + c] = p + __ldg(b2 + c);
    }
    grid_barrier(&g_bar2, GATE_BLOCKS);

    // -------- Softmax: blocks 0..7 handle batch rows 0..7 ------------------
    if (blockIdx.x < B) {
        const int bb = blockIdx.x;
        __shared__ float red[C];
        const float logit = g_logits[bb * C + tid];
        red[tid] = logit;
        __syncthreads();
        #pragma unroll
        for (int s = 128; s > 0; s >>= 1) {
            if (tid < s) red[tid] = fmaxf(red[tid], red[tid + s]);
            __syncthreads();
        }
        const float m = red[0];
        __syncthreads();
        const float e = __expf(logit - m);
        red[tid] = e;
        __syncthreads();
        #pragma unroll
        for (int s = 128; s > 0; s >>= 1) {
            if (tid < s) red[tid] += red[tid + s];
            __syncthreads();
        }
        g_scale[bb * C + tid] = 1.0f + e / red[0];
    }
}

// ---------------------------------------------------------------------------
// Node 2 — pure stream: y = x * scale[plane]. 4 float4/thread, front-batched.
// EXACTLY the R4 kernel (best measured stream). No sync, no atomics.
// ---------------------------------------------------------------------------
__global__ void __launch_bounds__(256) scale_kernel(const float4* __restrict__ x,
                                                    float4* __restrict__ y) {
    const int blk   = blockIdx.x;
    const int plane = blk >> 4;                      // / BLOCKS_PER_PLANE
    const float s   = __ldg(&g_scale[plane]);
    const size_t i0 = (size_t)blk * F4_PER_BLOCK + threadIdx.x;

    float4 v0 = __ldcs(x + i0);
    float4 v1 = __ldcs(x + i0 + 256);
    float4 v2 = __ldcs(x + i0 + 512);
    float4 v3 = __ldcs(x + i0 + 768);

    v0.x *= s; v0.y *= s; v0.z *= s; v0.w *= s;
    v1.x *= s; v1.y *= s; v1.z *= s; v1.w *= s;
    v2.x *= s; v2.y *= s; v2.z *= s; v2.w *= s;
    v3.x *= s; v3.y *= s; v3.z *= s; v3.w *= s;

    __stcs(y + i0,       v0);
    __stcs(y + i0 + 256, v1);
    __stcs(y + i0 + 512, v2);
    __stcs(y + i0 + 768, v3);
}

extern "C" void kernel_launch(void* const* d_in, const int* in_sizes, int n_in,
                              void* d_out, int out_size) {
    const float* x        = (const float*)d_in[0];
    const float* semantic = (const float*)d_in[1];
    const float* W1       = (const float*)d_in[2];
    const float* b1       = (const float*)d_in[3];
    const float* W2       = (const float*)d_in[4];
    const float* b2       = (const float*)d_in[5];
    float* out = (float*)d_out;

    gate_kernel<<<GATE_BLOCKS, 256>>>(semantic, W1, b1, W2, b2);

    const int nblocks = (B * C) * BLOCKS_PER_PLANE;   // 32768
    scale_kernel<<<nblocks, 256>>>((const float4*)x, (float4*)out);
}